// round 1
// baseline (speedup 1.0000x reference)
#include <cuda_runtime.h>

// RSI over rows of a 2048 x 8192 fp32 matrix.
// out[r][c] = 1 - 1/(1+rs), rs = avg_gain/avg_loss over window of w = window_size-1
// p[i] = (x[i+1]-x[i])/x[i] if x[i]!=0 else 0
//
// Pure HBM-streaming kernel: each input element read ~1.05x (halo), output
// written once. Shared-memory staged stencil so each division happens once.

#define NROWS 2048
#define NCOLS 8192
#define TPB   256
#define MAXW  64   // upper bound on (window_size-1) we support in smem sizing

__global__ __launch_bounds__(TPB) void rsi_kernel(
    const float* __restrict__ in,
    float* __restrict__ out,
    int out_cols,   // NCOLS - w
    int w)          // window_size - 1
{
    __shared__ float s_in[TPB + MAXW + 1];
    __shared__ float s_g [TPB + MAXW];
    __shared__ float s_l [TPB + MAXW];

    const int row  = blockIdx.y;
    const int base = blockIdx.x * TPB;           // first output col of this block
    const float* rin = in + (size_t)row * NCOLS;

    // Stage inputs [base, base + TPB + w] (clamped to row end).
    const int need_in = TPB + w + 1;
    for (int i = threadIdx.x; i < need_in; i += TPB) {
        const int col = base + i;
        s_in[i] = (col < NCOLS) ? rin[col] : 0.0f;
    }
    __syncthreads();

    // Compute gain/loss for p-indices [base, base + TPB + w - 1].
    // Out-of-range tail entries are garbage-but-finite and never consumed
    // by an in-range output.
    const int need_p = TPB + w;
    for (int i = threadIdx.x; i < need_p; i += TPB) {
        const float prev = s_in[i];
        const float cur  = s_in[i + 1];
        const float p = (prev != 0.0f) ? (cur - prev) / prev : 0.0f;
        s_g[i] = fmaxf(p, 0.0f);
        s_l[i] = fmaxf(-p, 0.0f);
    }
    __syncthreads();

    const int c = base + threadIdx.x;
    if (c < out_cols) {
        float g = 0.0f, l = 0.0f;
        #pragma unroll 13
        for (int j = 0; j < w; ++j) {
            g += s_g[threadIdx.x + j];
            l += s_l[threadIdx.x + j];
        }
        const float inv_w = 1.0f / (float)w;
        const float ag = g * inv_w;
        const float al = l * inv_w;
        const float rs = (al != 0.0f) ? ag / al : 0.0f;
        out[(size_t)row * out_cols + c] = 1.0f - 1.0f / (1.0f + rs);
    }
}

extern "C" void kernel_launch(void* const* d_in, const int* in_sizes, int n_in,
                              void* d_out, int out_size)
{
    const float* in  = (const float*)d_in[0];
    float*       out = (float*)d_out;

    // Derive window purely from sizes (no device read -> graph-capturable):
    // out_size = NROWS * (NCOLS - (window_size - 1))
    const int out_cols = out_size / NROWS;
    int w = NCOLS - out_cols;
    if (w < 1)    w = 1;
    if (w > MAXW) w = MAXW;   // smem bound guard (problem uses w = 13)

    dim3 grid((out_cols + TPB - 1) / TPB, NROWS);
    rsi_kernel<<<grid, TPB>>>(in, out, out_cols, w);
}

// round 2
// speedup vs baseline: 2.4518x; 2.4518x over previous
#include <cuda_runtime.h>

// RSI, fused single-pass. 2048 x 8192 fp32 input, out = g/(g+l) over sliding
// window of w = window_size-1 of positive/negative relative deltas.
//
// Issue-bound workload (R1 ncu: issue 85%, DRAM 8.6%) -> minimize instructions
// per output: 8 outputs/thread, thread-local prefix sums, skewed smem, float4
// staging, algebraically fused epilogue (1 division per output).

#define NROWS 2048
#define NCOLS 8192
#define TPB   256
#define ITEMS 8
#define TILE  (TPB * ITEMS)   // 2048 output columns per block
#define MAXW  64

__device__ __forceinline__ int skew(int i) { return i + (i >> 5); }

template <int W>
__global__ __launch_bounds__(TPB) void rsi_tiled(
    const float* __restrict__ in,
    float* __restrict__ out,
    int out_cols)
{
    constexpr int NP   = TILE + W - 1;            // p values this tile needs
    constexpr int NIN  = TILE + W;                // inputs staged
    constexpr int SKSZ = NP + (NP >> 5) + 2;

    __shared__ __align__(16) float s_in[NIN + 4];
    __shared__ float s_g[SKSZ];
    __shared__ float s_l[SKSZ];

    const int row  = blockIdx.y;
    const int base = blockIdx.x * TILE;
    const int tid  = threadIdx.x;
    const float* rin = in + (size_t)row * NCOLS;

    // ---- Stage inputs: float4 main body (always in-row: base+2047 <= 8191) ----
    const float4* rin4 = (const float4*)rin + (base >> 2);
    #pragma unroll
    for (int v = 0; v < TILE / 4 / TPB; ++v) {    // 2 iters
        const int idx = tid + v * TPB;
        ((float4*)s_in)[idx] = rin4[idx];
    }
    // halo (W scalars, clamp at row end)
    if (tid < W) {
        const int col = base + TILE + tid;
        s_in[TILE + tid] = (col < NCOLS) ? rin[col] : 0.0f;
    }
    __syncthreads();

    // ---- p -> gain/loss into skewed smem (one division per p-value) ----
    #pragma unroll
    for (int v = 0; v < TILE / TPB; ++v) {        // 8 iters
        const int i = tid + v * TPB;
        const float prev = s_in[i];
        const float cur  = s_in[i + 1];
        const float p = (prev != 0.0f) ? (cur - prev) / prev : 0.0f;
        const int si = skew(i);
        s_g[si] = fmaxf(p, 0.0f);
        s_l[si] = fmaxf(-p, 0.0f);
    }
    if (tid < NP - TILE) {                        // tail: W-1 values
        const int i = TILE + tid;
        const float prev = s_in[i];
        const float cur  = s_in[i + 1];
        const float p = (prev != 0.0f) ? (cur - prev) / prev : 0.0f;
        const int si = skew(i);
        s_g[si] = fmaxf(p, 0.0f);
        s_l[si] = fmaxf(-p, 0.0f);
    }
    __syncthreads();

    // ---- 8 sliding windows per thread via thread-local prefix sums ----
    const int lo = tid * ITEMS;
    float Pg = 0.0f, Pl = 0.0f;
    float qg[ITEMS], ql[ITEMS];
    float ov[ITEMS];

    #pragma unroll
    for (int j = 0; j < ITEMS + W - 1; ++j) {     // 20 iters (W=13)
        if (j < ITEMS) { qg[j] = Pg; ql[j] = Pl; }
        const int si = skew(lo + j);
        Pg += s_g[si];
        Pl += s_l[si];
        if (j >= W - 1) {
            const int k = j - (W - 1);
            const float g = Pg - qg[k];
            const float l = Pl - ql[k];
            // 1 - 1/(1+rs) with rs = (g/w)/(l/w)  ==  g/(g+l); 0 when l == 0
            ov[k] = (l != 0.0f) ? g / (g + l) : 0.0f;
        }
    }

    // ---- store 8 contiguous outputs ----
    const int c0 = base + lo;
    float* rout = out + (size_t)row * out_cols + c0;
    if (c0 + ITEMS <= out_cols) {
        #pragma unroll
        for (int k = 0; k < ITEMS; ++k) rout[k] = ov[k];
    } else {
        #pragma unroll
        for (int k = 0; k < ITEMS; ++k)
            if (c0 + k < out_cols) rout[k] = ov[k];
    }
}

// ---- Generic fallback for unexpected window sizes ----
__global__ __launch_bounds__(TPB) void rsi_generic(
    const float* __restrict__ in,
    float* __restrict__ out,
    int out_cols, int w)
{
    __shared__ float s_in[TPB + MAXW + 1];
    __shared__ float s_g [TPB + MAXW];
    __shared__ float s_l [TPB + MAXW];

    const int row  = blockIdx.y;
    const int base = blockIdx.x * TPB;
    const float* rin = in + (size_t)row * NCOLS;

    const int need_in = TPB + w + 1;
    for (int i = threadIdx.x; i < need_in; i += TPB) {
        const int col = base + i;
        s_in[i] = (col < NCOLS) ? rin[col] : 0.0f;
    }
    __syncthreads();

    const int need_p = TPB + w;
    for (int i = threadIdx.x; i < need_p; i += TPB) {
        const float prev = s_in[i];
        const float cur  = s_in[i + 1];
        const float p = (prev != 0.0f) ? (cur - prev) / prev : 0.0f;
        s_g[i] = fmaxf(p, 0.0f);
        s_l[i] = fmaxf(-p, 0.0f);
    }
    __syncthreads();

    const int c = base + threadIdx.x;
    if (c < out_cols) {
        float g = 0.0f, l = 0.0f;
        for (int j = 0; j < w; ++j) {
            g += s_g[threadIdx.x + j];
            l += s_l[threadIdx.x + j];
        }
        out[(size_t)row * out_cols + c] = (l != 0.0f) ? g / (g + l) : 0.0f;
    }
}

extern "C" void kernel_launch(void* const* d_in, const int* in_sizes, int n_in,
                              void* d_out, int out_size)
{
    const float* in  = (const float*)d_in[0];
    float*       out = (float*)d_out;

    const int out_cols = out_size / NROWS;        // NCOLS - (window_size-1)
    int w = NCOLS - out_cols;

    if (w == 13) {
        dim3 grid((out_cols + TILE - 1) / TILE, NROWS);
        rsi_tiled<13><<<grid, TPB>>>(in, out, out_cols);
    } else {
        if (w < 1)    w = 1;
        if (w > MAXW) w = MAXW;
        dim3 grid((out_cols + TPB - 1) / TPB, NROWS);
        rsi_generic<<<grid, TPB>>>(in, out, out_cols, w);
    }
}